// round 3
// baseline (speedup 1.0000x reference)
#include <cuda_runtime.h>
#include <stdint.h>

// Problem shape (fixed by setup_inputs):
// B=1024, K=4, E=16, H=2048, I=2048
#define NE   16
#define HD   2048
#define ID   2048
#define I2D  4096
#define NP   4096      // B*K token-expert pairs
#define TOPK 4

#define BM  64
#define BN  64
#define BKS 16

// Scratch (allocation-free rule: __device__ globals)
__device__ int   d_cnt[NE];
__device__ int   d_bucket[NE][NP];
__device__ float d_g[(size_t)NP * ID];   // 32 MB swiglu activations

union F2 { unsigned long long u; float2 f; };

__device__ __forceinline__ void fma2(unsigned long long& d,
                                     unsigned long long a,
                                     unsigned long long b) {
    // packed fp32x2 FMA: 2 FMAs per instruction on sm_103a
    asm("fma.rn.f32x2 %0, %1, %2, %0;" : "+l"(d) : "l"(a), "l"(b));
}

__device__ __forceinline__ float swiglu_pair(float xg, float xl) {
    xg = fminf(xg, 7.0f);
    xl = fminf(fmaxf(xl, -7.0f), 7.0f);
    float s = 1.0f / (1.0f + __expf(-1.702f * xg));
    return xg * s * (xl + 1.0f);
}

__global__ void zero_cnt_kernel() {
    if (threadIdx.x < NE) d_cnt[threadIdx.x] = 0;
}

__global__ void scatter_kernel(const int* __restrict__ idx) {
    int p = blockIdx.x * blockDim.x + threadIdx.x;
    if (p < NP) {
        int e = idx[p];
        int pos = atomicAdd(&d_cnt[e], 1);
        d_bucket[e][pos] = p;
    }
}

// C[m, c] = sum_k T[token(m), k] * W1[e, c, k]  (+bias, then fused swiglu)
// Writes g[p, 0..I) to d_g.
__global__ __launch_bounds__(256, 2) void gate_up_kernel(
    const float* __restrict__ t,
    const float* __restrict__ w,      // (E, 2I, H)
    const float* __restrict__ bias)   // (E, 2I)
{
    int e  = blockIdx.z;
    int M  = d_cnt[e];
    int m0 = blockIdx.y * BM;
    if (m0 >= M) return;
    int n0 = blockIdx.x * BN;

    __shared__ float As[BKS][BM];
    __shared__ float Bs[BKS][BN];
    __shared__ int   ps[BM];

    int tid = threadIdx.x;
    if (tid < BM) {
        int r = m0 + tid;
        ps[tid] = (r < M) ? d_bucket[e][r] : -1;
    }
    __syncthreads();

    int lr = tid >> 2;           // 0..63 row for loading
    int ls = (tid & 3) * 4;      // k segment start
    int pRow = ps[lr];
    bool aval = (pRow >= 0);
    const float* aptr = t + (size_t)(aval ? (pRow >> 2) : 0) * HD + ls;
    const float* bptr = w + ((size_t)e * I2D + n0 + lr) * HD + ls;

    int ty = tid >> 4;           // 0..15 -> rows ty*4
    int tx = tid & 15;           // 0..15 -> cols tx*4

    F2 acc[4][2];
#pragma unroll
    for (int i = 0; i < 4; i++) { acc[i][0].u = 0ULL; acc[i][1].u = 0ULL; }

    for (int k0 = 0; k0 < HD; k0 += BKS) {
        float4 av = make_float4(0.f, 0.f, 0.f, 0.f);
        if (aval) av = *(const float4*)(aptr + k0);
        float4 bv = *(const float4*)(bptr + k0);
        __syncthreads();
        As[ls + 0][lr] = av.x; As[ls + 1][lr] = av.y;
        As[ls + 2][lr] = av.z; As[ls + 3][lr] = av.w;
        Bs[ls + 0][lr] = bv.x; Bs[ls + 1][lr] = bv.y;
        Bs[ls + 2][lr] = bv.z; Bs[ls + 3][lr] = bv.w;
        __syncthreads();
#pragma unroll
        for (int k = 0; k < BKS; k++) {
            float4 a4 = *(const float4*)&As[k][ty * 4];
            float4 b4 = *(const float4*)&Bs[k][tx * 4];
            F2 b0, b1, a0, a1, a2, a3;
            b0.f = make_float2(b4.x, b4.y);
            b1.f = make_float2(b4.z, b4.w);
            a0.f = make_float2(a4.x, a4.x);
            a1.f = make_float2(a4.y, a4.y);
            a2.f = make_float2(a4.z, a4.z);
            a3.f = make_float2(a4.w, a4.w);
            fma2(acc[0][0].u, a0.u, b0.u); fma2(acc[0][1].u, a0.u, b1.u);
            fma2(acc[1][0].u, a1.u, b0.u); fma2(acc[1][1].u, a1.u, b1.u);
            fma2(acc[2][0].u, a2.u, b0.u); fma2(acc[2][1].u, a2.u, b1.u);
            fma2(acc[3][0].u, a3.u, b0.u); fma2(acc[3][1].u, a3.u, b1.u);
        }
    }

    int colBase = n0 + tx * 4;   // even; pairs (c, c+1) both in this thread
    float4 bb = *(const float4*)(bias + (size_t)e * I2D + colBase);
#pragma unroll
    for (int i = 0; i < 4; i++) {
        int r = ty * 4 + i;
        if (m0 + r < M) {
            int p = ps[r];
            float v0 = acc[i][0].f.x + bb.x;
            float v1 = acc[i][0].f.y + bb.y;
            float v2 = acc[i][1].f.x + bb.z;
            float v3 = acc[i][1].f.y + bb.w;
            float2 g;
            g.x = swiglu_pair(v0, v1);
            g.y = swiglu_pair(v2, v3);
            *(float2*)&d_g[(size_t)p * ID + (colBase >> 1)] = g;
        }
    }
}

// out[p, c] = sum_i W2[e, c, i] * g[p, i] + bias2[e, c]
__global__ __launch_bounds__(256, 2) void down_kernel(
    const float* __restrict__ w,      // (E, H, I)
    const float* __restrict__ bias,   // (E, H)
    float* __restrict__ out)          // (B, K, H) == (p, H)
{
    int e  = blockIdx.z;
    int M  = d_cnt[e];
    int m0 = blockIdx.y * BM;
    if (m0 >= M) return;
    int n0 = blockIdx.x * BN;

    __shared__ float As[BKS][BM];
    __shared__ float Bs[BKS][BN];
    __shared__ int   ps[BM];

    int tid = threadIdx.x;
    if (tid < BM) {
        int r = m0 + tid;
        ps[tid] = (r < M) ? d_bucket[e][r] : -1;
    }
    __syncthreads();

    int lr = tid >> 2;
    int ls = (tid & 3) * 4;
    int pRow = ps[lr];
    bool aval = (pRow >= 0);
    const float* aptr = d_g + (size_t)(aval ? pRow : 0) * ID + ls;
    const float* bptr = w + ((size_t)e * HD + n0 + lr) * ID + ls;

    int ty = tid >> 4;
    int tx = tid & 15;

    F2 acc[4][2];
#pragma unroll
    for (int i = 0; i < 4; i++) { acc[i][0].u = 0ULL; acc[i][1].u = 0ULL; }

    for (int k0 = 0; k0 < ID; k0 += BKS) {
        float4 av = make_float4(0.f, 0.f, 0.f, 0.f);
        if (aval) av = *(const float4*)(aptr + k0);
        float4 bv = *(const float4*)(bptr + k0);
        __syncthreads();
        As[ls + 0][lr] = av.x; As[ls + 1][lr] = av.y;
        As[ls + 2][lr] = av.z; As[ls + 3][lr] = av.w;
        Bs[ls + 0][lr] = bv.x; Bs[ls + 1][lr] = bv.y;
        Bs[ls + 2][lr] = bv.z; Bs[ls + 3][lr] = bv.w;
        __syncthreads();
#pragma unroll
        for (int k = 0; k < BKS; k++) {
            float4 a4 = *(const float4*)&As[k][ty * 4];
            float4 b4 = *(const float4*)&Bs[k][tx * 4];
            F2 b0, b1, a0, a1, a2, a3;
            b0.f = make_float2(b4.x, b4.y);
            b1.f = make_float2(b4.z, b4.w);
            a0.f = make_float2(a4.x, a4.x);
            a1.f = make_float2(a4.y, a4.y);
            a2.f = make_float2(a4.z, a4.z);
            a3.f = make_float2(a4.w, a4.w);
            fma2(acc[0][0].u, a0.u, b0.u); fma2(acc[0][1].u, a0.u, b1.u);
            fma2(acc[1][0].u, a1.u, b0.u); fma2(acc[1][1].u, a1.u, b1.u);
            fma2(acc[2][0].u, a2.u, b0.u); fma2(acc[2][1].u, a2.u, b1.u);
            fma2(acc[3][0].u, a3.u, b0.u); fma2(acc[3][1].u, a3.u, b1.u);
        }
    }

    int colBase = n0 + tx * 4;
    float4 bb = *(const float4*)(bias + (size_t)e * HD + colBase);
#pragma unroll
    for (int i = 0; i < 4; i++) {
        int r = ty * 4 + i;
        if (m0 + r < M) {
            int p = ps[r];
            float4 o;
            o.x = acc[i][0].f.x + bb.x;
            o.y = acc[i][0].f.y + bb.y;
            o.z = acc[i][1].f.x + bb.z;
            o.w = acc[i][1].f.y + bb.w;
            *(float4*)&out[(size_t)p * HD + colBase] = o;
        }
    }
}

extern "C" void kernel_launch(void* const* d_in, const int* in_sizes, int n_in,
                              void* d_out, int out_size) {
    const float* t   = (const float*)d_in[0];
    const int*   idx = (const int*)d_in[1];
    const float* w1  = (const float*)d_in[2];
    const float* b1  = (const float*)d_in[3];
    const float* w2  = (const float*)d_in[4];
    const float* b2  = (const float*)d_in[5];
    float* out = (float*)d_out;

    zero_cnt_kernel<<<1, 32>>>();
    scatter_kernel<<<NP / 256, 256>>>(idx);
    gate_up_kernel<<<dim3(I2D / BN, NP / BM, NE), 256>>>(t, w1, b1);
    down_kernel<<<dim3(HD / BN, NP / BM, NE), 256>>>(w2, b2, out);
}

// round 4
// speedup vs baseline: 1.2125x; 1.2125x over previous
#include <cuda_runtime.h>
#include <stdint.h>

// Problem shape (fixed by setup_inputs):
// B=1024, K=4, E=16, H=2048, I=2048
#define NE   16
#define HD   2048
#define ID   2048
#define I2D  4096
#define NP   4096      // B*K token-expert pairs

#define BM   128
#define BN   128
#define BK   16
#define PAD  132       // padded float stride (multiple of 4 for float4 alignment)

// Scratch (allocation-free rule: __device__ globals)
__device__ int   d_cnt[NE];
__device__ int   d_bucket[NE][NP];
__device__ float d_g[(size_t)NP * ID];   // 32 MB swiglu activations

union F2 { unsigned long long u; float2 f; };

__device__ __forceinline__ void fma2(unsigned long long& d,
                                     unsigned long long a,
                                     unsigned long long b) {
    // packed fp32x2 FMA: 2 FMAs per instruction on sm_103a
    asm("fma.rn.f32x2 %0, %1, %2, %0;" : "+l"(d) : "l"(a), "l"(b));
}

__device__ __forceinline__ float swiglu_pair(float xg, float xl) {
    xg = fminf(xg, 7.0f);
    xl = fminf(fmaxf(xl, -7.0f), 7.0f);
    float s = 1.0f / (1.0f + __expf(-1.702f * xg));
    return xg * s * (xl + 1.0f);
}

__global__ void zero_cnt_kernel() {
    if (threadIdx.x < NE) d_cnt[threadIdx.x] = 0;
}

__global__ void scatter_kernel(const int* __restrict__ idx) {
    int p = blockIdx.x * blockDim.x + threadIdx.x;
    if (p < NP) {
        int e = idx[p];
        int pos = atomicAdd(&d_cnt[e], 1);
        d_bucket[e][pos] = p;
    }
}

// ---------------------------------------------------------------------------
// Shared compute core: 128x128 tile, 8x8 microtile, packed f32x2 FMAs.
// A source row for local row m is ps[m] (-1 => zero row).
// ---------------------------------------------------------------------------

#define GEMM_BODY(A_ROW_PTR, KD_, B_BASE)                                      \
    __shared__ float As[BK * PAD];                                             \
    __shared__ float Bs[BK * PAD];                                             \
    __shared__ int   ps[BM];                                                   \
    int tid = threadIdx.x;                                                     \
    if (tid < BM) {                                                            \
        int r = m0 + tid;                                                      \
        ps[tid] = (r < M) ? d_bucket[e][r] : -1;                               \
    }                                                                          \
    __syncthreads();                                                           \
    const int mA0 = tid >> 2;                                                  \
    const int mA1 = mA0 + 64;                                                  \
    const int seg = (tid & 3) * 4;                                             \
    const int p0 = ps[mA0];                                                    \
    const int p1 = ps[mA1];                                                    \
    const float* aSrc0 = (p0 >= 0) ? (A_ROW_PTR(p0)) + seg : 0;                \
    const float* aSrc1 = (p1 >= 0) ? (A_ROW_PTR(p1)) + seg : 0;                \
    const float* bSrc0 = (B_BASE) + (size_t)mA0 * (KD_) + seg;                 \
    const float* bSrc1 = (B_BASE) + (size_t)mA1 * (KD_) + seg;                 \
    const int ty = tid >> 4;                                                   \
    const int tx = tid & 15;                                                   \
    F2 acc[8][4];                                                              \
    _Pragma("unroll")                                                          \
    for (int i = 0; i < 8; i++) {                                              \
        acc[i][0].u = 0ULL; acc[i][1].u = 0ULL;                                \
        acc[i][2].u = 0ULL; acc[i][3].u = 0ULL;                                \
    }                                                                          \
    float4 rA0, rA1, rB0, rB1;                                                 \
    const float4 fz = make_float4(0.f, 0.f, 0.f, 0.f);                         \
    rA0 = aSrc0 ? *(const float4*)(aSrc0) : fz;                                \
    rA1 = aSrc1 ? *(const float4*)(aSrc1) : fz;                                \
    rB0 = *(const float4*)(bSrc0);                                             \
    rB1 = *(const float4*)(bSrc1);                                             \
    for (int k0 = 0; k0 < (KD_); k0 += BK) {                                   \
        As[(seg + 0) * PAD + mA0] = rA0.x; As[(seg + 1) * PAD + mA0] = rA0.y;  \
        As[(seg + 2) * PAD + mA0] = rA0.z; As[(seg + 3) * PAD + mA0] = rA0.w;  \
        As[(seg + 0) * PAD + mA1] = rA1.x; As[(seg + 1) * PAD + mA1] = rA1.y;  \
        As[(seg + 2) * PAD + mA1] = rA1.z; As[(seg + 3) * PAD + mA1] = rA1.w;  \
        Bs[(seg + 0) * PAD + mA0] = rB0.x; Bs[(seg + 1) * PAD + mA0] = rB0.y;  \
        Bs[(seg + 2) * PAD + mA0] = rB0.z; Bs[(seg + 3) * PAD + mA0] = rB0.w;  \
        Bs[(seg + 0) * PAD + mA1] = rB1.x; Bs[(seg + 1) * PAD + mA1] = rB1.y;  \
        Bs[(seg + 2) * PAD + mA1] = rB1.z; Bs[(seg + 3) * PAD + mA1] = rB1.w;  \
        __syncthreads();                                                       \
        if (k0 + BK < (KD_)) {                                                 \
            rA0 = aSrc0 ? *(const float4*)(aSrc0 + k0 + BK) : fz;              \
            rA1 = aSrc1 ? *(const float4*)(aSrc1 + k0 + BK) : fz;              \
            rB0 = *(const float4*)(bSrc0 + k0 + BK);                           \
            rB1 = *(const float4*)(bSrc1 + k0 + BK);                           \
        }                                                                      \
        _Pragma("unroll")                                                      \
        for (int k = 0; k < BK; ++k) {                                         \
            const float* arow = &As[k * PAD + ty * 8];                         \
            const float* brow = &Bs[k * PAD + tx * 8];                         \
            float4 aA = *(const float4*)arow;                                  \
            float4 aB = *(const float4*)(arow + 4);                            \
            float4 bA = *(const float4*)brow;                                  \
            float4 bB = *(const float4*)(brow + 4);                            \
            F2 bb0, bb1, bb2, bb3;                                             \
            bb0.f = make_float2(bA.x, bA.y);                                   \
            bb1.f = make_float2(bA.z, bA.w);                                   \
            bb2.f = make_float2(bB.x, bB.y);                                   \
            bb3.f = make_float2(bB.z, bB.w);                                   \
            float aa[8] = {aA.x, aA.y, aA.z, aA.w, aB.x, aB.y, aB.z, aB.w};    \
            _Pragma("unroll")                                                  \
            for (int i = 0; i < 8; ++i) {                                      \
                F2 ai; ai.f = make_float2(aa[i], aa[i]);                       \
                fma2(acc[i][0].u, ai.u, bb0.u);                                \
                fma2(acc[i][1].u, ai.u, bb1.u);                                \
                fma2(acc[i][2].u, ai.u, bb2.u);                                \
                fma2(acc[i][3].u, ai.u, bb3.u);                                \
            }                                                                  \
        }                                                                      \
        __syncthreads();                                                       \
    }

// C[m, c] = sum_k T[token(m), k] * W1[e, c, k]  (+bias, fused swiglu -> d_g)
#define A_ROW_GATE(p) (t + (size_t)((p) >> 2) * HD)
__global__ __launch_bounds__(256, 2) void gate_up_kernel(
    const float* __restrict__ t,
    const float* __restrict__ w,      // (E, 2I, H)
    const float* __restrict__ bias)   // (E, 2I)
{
    const int e  = blockIdx.z;
    const int M  = d_cnt[e];
    const int m0 = blockIdx.y * BM;
    if (m0 >= M) return;
    const int n0 = blockIdx.x * BN;
    const float* bBase = w + ((size_t)e * I2D + n0) * HD;

    GEMM_BODY(A_ROW_GATE, HD, bBase)

    const int colBase = n0 + tx * 8;  // 8 cols = 4 (glu,lin) pairs
    float4 bbi0 = *(const float4*)(bias + (size_t)e * I2D + colBase);
    float4 bbi1 = *(const float4*)(bias + (size_t)e * I2D + colBase + 4);
#pragma unroll
    for (int i = 0; i < 8; i++) {
        int r = ty * 8 + i;
        if (m0 + r < M) {
            int p = ps[r];
            float v0 = acc[i][0].f.x + bbi0.x;
            float v1 = acc[i][0].f.y + bbi0.y;
            float v2 = acc[i][1].f.x + bbi0.z;
            float v3 = acc[i][1].f.y + bbi0.w;
            float v4 = acc[i][2].f.x + bbi1.x;
            float v5 = acc[i][2].f.y + bbi1.y;
            float v6 = acc[i][3].f.x + bbi1.z;
            float v7 = acc[i][3].f.y + bbi1.w;
            float4 g;
            g.x = swiglu_pair(v0, v1);
            g.y = swiglu_pair(v2, v3);
            g.z = swiglu_pair(v4, v5);
            g.w = swiglu_pair(v6, v7);
            *(float4*)&d_g[(size_t)p * ID + (colBase >> 1)] = g;
        }
    }
}

// out[p, c] = sum_i W2[e, c, i] * g[p, i] + bias2[e, c]
#define A_ROW_DOWN(p) (g_act + (size_t)(p) * ID)
__global__ __launch_bounds__(256, 2) void down_kernel(
    const float* __restrict__ w,      // (E, H, I)
    const float* __restrict__ bias,   // (E, H)
    float* __restrict__ out)          // (p, H)
{
    const int e  = blockIdx.z;
    const int M  = d_cnt[e];
    const int m0 = blockIdx.y * BM;
    if (m0 >= M) return;
    const int n0 = blockIdx.x * BN;
    const float* g_act = d_g;
    const float* bBase = w + ((size_t)e * HD + n0) * ID;

    GEMM_BODY(A_ROW_DOWN, ID, bBase)

    const int colBase = n0 + tx * 8;
    float4 bbi0 = *(const float4*)(bias + (size_t)e * HD + colBase);
    float4 bbi1 = *(const float4*)(bias + (size_t)e * HD + colBase + 4);
#pragma unroll
    for (int i = 0; i < 8; i++) {
        int r = ty * 8 + i;
        if (m0 + r < M) {
            int p = ps[r];
            float4 o0, o1;
            o0.x = acc[i][0].f.x + bbi0.x;
            o0.y = acc[i][0].f.y + bbi0.y;
            o0.z = acc[i][1].f.x + bbi0.z;
            o0.w = acc[i][1].f.y + bbi0.w;
            o1.x = acc[i][2].f.x + bbi1.x;
            o1.y = acc[i][2].f.y + bbi1.y;
            o1.z = acc[i][3].f.x + bbi1.z;
            o1.w = acc[i][3].f.y + bbi1.w;
            *(float4*)&out[(size_t)p * HD + colBase]     = o0;
            *(float4*)&out[(size_t)p * HD + colBase + 4] = o1;
        }
    }
}

extern "C" void kernel_launch(void* const* d_in, const int* in_sizes, int n_in,
                              void* d_out, int out_size) {
    const float* t   = (const float*)d_in[0];
    const int*   idx = (const int*)d_in[1];
    const float* w1  = (const float*)d_in[2];
    const float* b1  = (const float*)d_in[3];
    const float* w2  = (const float*)d_in[4];
    const float* b2  = (const float*)d_in[5];
    float* out = (float*)d_out;

    zero_cnt_kernel<<<1, 32>>>();
    scatter_kernel<<<NP / 256, 256>>>(idx);
    gate_up_kernel<<<dim3(I2D / BN, NP / BM, NE), 256>>>(t, w1, b1);
    down_kernel<<<dim3(HD / BN, NP / BM, NE), 256>>>(w2, b2, out);
}

// round 5
// speedup vs baseline: 1.2139x; 1.0011x over previous
#include <cuda_runtime.h>
#include <stdint.h>

// Problem shape (fixed by setup_inputs):
// B=1024, K=4, E=16, H=2048, I=2048
#define NE   16
#define HD   2048
#define ID   2048
#define I2D  4096
#define NP   4096      // B*K token-expert pairs

#define BM   128
#define BN   128
#define BK   16
#define PAD  132       // padded float stride (multiple of 4 for float4 alignment)

// Scratch (allocation-free rule: __device__ globals)
__device__ int   d_cnt[NE];
__device__ int   d_bucket[NE][NP];
__device__ float d_g[(size_t)NP * ID];   // 32 MB swiglu activations

union F2 { unsigned long long u; float2 f; };

__device__ __forceinline__ void fma2(unsigned long long& d,
                                     unsigned long long a,
                                     unsigned long long b) {
    // packed fp32x2 FMA: 2 FMAs per instruction on sm_103a
    asm("fma.rn.f32x2 %0, %1, %2, %0;" : "+l"(d) : "l"(a), "l"(b));
}

__device__ __forceinline__ float swiglu_pair(float xg, float xl) {
    xg = fminf(xg, 7.0f);
    xl = fminf(fmaxf(xl, -7.0f), 7.0f);
    float s = 1.0f / (1.0f + __expf(-1.702f * xg));
    return xg * s * (xl + 1.0f);
}

__global__ void zero_cnt_kernel() {
    if (threadIdx.x < NE) d_cnt[threadIdx.x] = 0;
}

__global__ void scatter_kernel(const int* __restrict__ idx) {
    int p = blockIdx.x * blockDim.x + threadIdx.x;
    if (p < NP) {
        int e = idx[p];
        int pos = atomicAdd(&d_cnt[e], 1);
        d_bucket[e][pos] = p;
    }
}

// ---------------------------------------------------------------------------
// Shared compute core: 128x128 tile, 8x8 microtile, packed f32x2 FMAs.
// A source row for local row m is ps[m] (-1 => zero row).
// ---------------------------------------------------------------------------

#define GEMM_BODY(A_ROW_PTR, KD_, B_BASE)                                      \
    __shared__ float As[BK * PAD];                                             \
    __shared__ float Bs[BK * PAD];                                             \
    __shared__ int   ps[BM];                                                   \
    int tid = threadIdx.x;                                                     \
    if (tid < BM) {                                                            \
        int r = m0 + tid;                                                      \
        ps[tid] = (r < M) ? d_bucket[e][r] : -1;                               \
    }                                                                          \
    __syncthreads();                                                           \
    const int mA0 = tid >> 2;                                                  \
    const int mA1 = mA0 + 64;                                                  \
    const int seg = (tid & 3) * 4;                                             \
    const int p0 = ps[mA0];                                                    \
    const int p1 = ps[mA1];                                                    \
    const float* aSrc0 = (p0 >= 0) ? (A_ROW_PTR(p0)) + seg : 0;                \
    const float* aSrc1 = (p1 >= 0) ? (A_ROW_PTR(p1)) + seg : 0;                \
    const float* bSrc0 = (B_BASE) + (size_t)mA0 * (KD_) + seg;                 \
    const float* bSrc1 = (B_BASE) + (size_t)mA1 * (KD_) + seg;                 \
    const int ty = tid >> 4;                                                   \
    const int tx = tid & 15;                                                   \
    F2 acc[8][4];                                                              \
    _Pragma("unroll")                                                          \
    for (int i = 0; i < 8; i++) {                                              \
        acc[i][0].u = 0ULL; acc[i][1].u = 0ULL;                                \
        acc[i][2].u = 0ULL; acc[i][3].u = 0ULL;                                \
    }                                                                          \
    float4 rA0, rA1, rB0, rB1;                                                 \
    const float4 fz = make_float4(0.f, 0.f, 0.f, 0.f);                         \
    rA0 = aSrc0 ? *(const float4*)(aSrc0) : fz;                                \
    rA1 = aSrc1 ? *(const float4*)(aSrc1) : fz;                                \
    rB0 = *(const float4*)(bSrc0);                                             \
    rB1 = *(const float4*)(bSrc1);                                             \
    for (int k0 = 0; k0 < (KD_); k0 += BK) {                                   \
        As[(seg + 0) * PAD + mA0] = rA0.x; As[(seg + 1) * PAD + mA0] = rA0.y;  \
        As[(seg + 2) * PAD + mA0] = rA0.z; As[(seg + 3) * PAD + mA0] = rA0.w;  \
        As[(seg + 0) * PAD + mA1] = rA1.x; As[(seg + 1) * PAD + mA1] = rA1.y;  \
        As[(seg + 2) * PAD + mA1] = rA1.z; As[(seg + 3) * PAD + mA1] = rA1.w;  \
        Bs[(seg + 0) * PAD + mA0] = rB0.x; Bs[(seg + 1) * PAD + mA0] = rB0.y;  \
        Bs[(seg + 2) * PAD + mA0] = rB0.z; Bs[(seg + 3) * PAD + mA0] = rB0.w;  \
        Bs[(seg + 0) * PAD + mA1] = rB1.x; Bs[(seg + 1) * PAD + mA1] = rB1.y;  \
        Bs[(seg + 2) * PAD + mA1] = rB1.z; Bs[(seg + 3) * PAD + mA1] = rB1.w;  \
        __syncthreads();                                                       \
        if (k0 + BK < (KD_)) {                                                 \
            rA0 = aSrc0 ? *(const float4*)(aSrc0 + k0 + BK) : fz;              \
            rA1 = aSrc1 ? *(const float4*)(aSrc1 + k0 + BK) : fz;              \
            rB0 = *(const float4*)(bSrc0 + k0 + BK);                           \
            rB1 = *(const float4*)(bSrc1 + k0 + BK);                           \
        }                                                                      \
        _Pragma("unroll")                                                      \
        for (int k = 0; k < BK; ++k) {                                         \
            const float* arow = &As[k * PAD + ty * 8];                         \
            const float* brow = &Bs[k * PAD + tx * 8];                         \
            float4 aA = *(const float4*)arow;                                  \
            float4 aB = *(const float4*)(arow + 4);                            \
            float4 bA = *(const float4*)brow;                                  \
            float4 bB = *(const float4*)(brow + 4);                            \
            F2 bb0, bb1, bb2, bb3;                                             \
            bb0.f = make_float2(bA.x, bA.y);                                   \
            bb1.f = make_float2(bA.z, bA.w);                                   \
            bb2.f = make_float2(bB.x, bB.y);                                   \
            bb3.f = make_float2(bB.z, bB.w);                                   \
            float aa[8] = {aA.x, aA.y, aA.z, aA.w, aB.x, aB.y, aB.z, aB.w};    \
            _Pragma("unroll")                                                  \
            for (int i = 0; i < 8; ++i) {                                      \
                F2 ai; ai.f = make_float2(aa[i], aa[i]);                       \
                fma2(acc[i][0].u, ai.u, bb0.u);                                \
                fma2(acc[i][1].u, ai.u, bb1.u);                                \
                fma2(acc[i][2].u, ai.u, bb2.u);                                \
                fma2(acc[i][3].u, ai.u, bb3.u);                                \
            }                                                                  \
        }                                                                      \
        __syncthreads();                                                       \
    }

// C[m, c] = sum_k T[token(m), k] * W1[e, c, k]  (+bias, fused swiglu -> d_g)
#define A_ROW_GATE(p) (t + (size_t)((p) >> 2) * HD)
__global__ __launch_bounds__(256, 2) void gate_up_kernel(
    const float* __restrict__ t,
    const float* __restrict__ w,      // (E, 2I, H)
    const float* __restrict__ bias)   // (E, 2I)
{
    const int e  = blockIdx.z;
    const int M  = d_cnt[e];
    const int m0 = blockIdx.y * BM;
    if (m0 >= M) return;
    const int n0 = blockIdx.x * BN;
    const float* bBase = w + ((size_t)e * I2D + n0) * HD;

    GEMM_BODY(A_ROW_GATE, HD, bBase)

    const int colBase = n0 + tx * 8;  // 8 cols = 4 (glu,lin) pairs
    float4 bbi0 = *(const float4*)(bias + (size_t)e * I2D + colBase);
    float4 bbi1 = *(const float4*)(bias + (size_t)e * I2D + colBase + 4);
#pragma unroll
    for (int i = 0; i < 8; i++) {
        int r = ty * 8 + i;
        if (m0 + r < M) {
            int p = ps[r];
            float v0 = acc[i][0].f.x + bbi0.x;
            float v1 = acc[i][0].f.y + bbi0.y;
            float v2 = acc[i][1].f.x + bbi0.z;
            float v3 = acc[i][1].f.y + bbi0.w;
            float v4 = acc[i][2].f.x + bbi1.x;
            float v5 = acc[i][2].f.y + bbi1.y;
            float v6 = acc[i][3].f.x + bbi1.z;
            float v7 = acc[i][3].f.y + bbi1.w;
            float4 g;
            g.x = swiglu_pair(v0, v1);
            g.y = swiglu_pair(v2, v3);
            g.z = swiglu_pair(v4, v5);
            g.w = swiglu_pair(v6, v7);
            *(float4*)&d_g[(size_t)p * ID + (colBase >> 1)] = g;
        }
    }
}

// out[p, c] = sum_i W2[e, c, i] * g[p, i] + bias2[e, c]
#define A_ROW_DOWN(p) (g_act + (size_t)(p) * ID)
__global__ __launch_bounds__(256, 2) void down_kernel(
    const float* __restrict__ w,      // (E, H, I)
    const float* __restrict__ bias,   // (E, H)
    float* __restrict__ out)          // (p, H)
{
    const int e  = blockIdx.z;
    const int M  = d_cnt[e];
    const int m0 = blockIdx.y * BM;
    if (m0 >= M) return;
    const int n0 = blockIdx.x * BN;
    const float* g_act = d_g;
    const float* bBase = w + ((size_t)e * HD + n0) * ID;

    GEMM_BODY(A_ROW_DOWN, ID, bBase)

    const int colBase = n0 + tx * 8;
    float4 bbi0 = *(const float4*)(bias + (size_t)e * HD + colBase);
    float4 bbi1 = *(const float4*)(bias + (size_t)e * HD + colBase + 4);
#pragma unroll
    for (int i = 0; i < 8; i++) {
        int r = ty * 8 + i;
        if (m0 + r < M) {
            int p = ps[r];
            float4 o0, o1;
            o0.x = acc[i][0].f.x + bbi0.x;
            o0.y = acc[i][0].f.y + bbi0.y;
            o0.z = acc[i][1].f.x + bbi0.z;
            o0.w = acc[i][1].f.y + bbi0.w;
            o1.x = acc[i][2].f.x + bbi1.x;
            o1.y = acc[i][2].f.y + bbi1.y;
            o1.z = acc[i][3].f.x + bbi1.z;
            o1.w = acc[i][3].f.y + bbi1.w;
            *(float4*)&out[(size_t)p * HD + colBase]     = o0;
            *(float4*)&out[(size_t)p * HD + colBase + 4] = o1;
        }
    }
}

extern "C" void kernel_launch(void* const* d_in, const int* in_sizes, int n_in,
                              void* d_out, int out_size) {
    const float* t   = (const float*)d_in[0];
    const int*   idx = (const int*)d_in[1];
    const float* w1  = (const float*)d_in[2];
    const float* b1  = (const float*)d_in[3];
    const float* w2  = (const float*)d_in[4];
    const float* b2  = (const float*)d_in[5];
    float* out = (float*)d_out;

    zero_cnt_kernel<<<1, 32>>>();
    scatter_kernel<<<NP / 256, 256>>>(idx);
    gate_up_kernel<<<dim3(I2D / BN, NP / BM, NE), 256>>>(t, w1, b1);
    down_kernel<<<dim3(HD / BN, NP / BM, NE), 256>>>(w2, b2, out);
}